// round 8
// baseline (speedup 1.0000x reference)
#include <cuda_runtime.h>
#include <cuda_bf16.h>
#include <cuda_fp16.h>
#include <cstdint>

#define N_NODES 100000
#define N_EDGES 1600000
#define FEAT 128
#define SCAN_BLK 1024
#define N_SBLK ((N_NODES + SCAN_BLK - 1) / SCAN_BLK)   // 98

#define G_GEMM ((N_NODES + 127) / 128)                 // 782 gemm tile blocks
#define G_FILL 1266                                    // fill blocks in fused grid

// Scratch (static device globals — no allocation).
__device__ __half g_xw[(size_t)N_NODES * FEAT];  // 25.6 MB (fp16 xw)
__device__ float g_dis[N_NODES];
__device__ int   g_degi[N_NODES];
__device__ int   g_base[N_NODES];
__device__ int   g_cur[N_NODES];
__device__ unsigned long long g_sstat[N_SBLK];   // decoupled-lookback status
__device__ int   g_src[N_EDGES];
__device__ int   g_is64;
// W transposed to [n][k], split to bf16 hi/lo, k-pairs packed in uint32.
__device__ uint32_t g_Whi[128 * 64];
__device__ uint32_t g_Wlo[128 * 64];

// ---------------------------------------------------------------------------
__device__ __forceinline__ long long edge_at(const void* p, long long i) {
    if (g_is64) return ((const long long*)p)[i];
    return (long long)((const int*)p)[i];
}

// Fused: blocks [0,391) zero degi + scan status (+detect int64 in block 0);
//        blocks [391,423) transpose/split W into bf16 hi/lo packed images.
__global__ void init_wprep_kernel(const unsigned int* __restrict__ w,
                                  const float* __restrict__ W) {
    if (blockIdx.x < 391) {
        int i = blockIdx.x * blockDim.x + threadIdx.x;
        if (i < N_NODES) g_degi[i] = 0;
        if (i < N_SBLK) g_sstat[i] = 0ULL;
        if (blockIdx.x == 0 && threadIdx.x == 0) {
            int is64 = 1;
            for (int k = 0; k < 64; k++)
                if (w[2 * k + 1] != 0u) { is64 = 0; break; }
            g_is64 = is64;
        }
    } else {
        int idx = (blockIdx.x - 391) * blockDim.x + threadIdx.x;  // 0..8191
        if (idx >= 8192) return;
        int n  = idx >> 6;
        int kp = idx & 63;
        float v0 = W[(size_t)(2 * kp) * FEAT + n];
        float v1 = W[(size_t)(2 * kp + 1) * FEAT + n];
        __nv_bfloat16 h0 = __float2bfloat16(v0);
        __nv_bfloat16 h1 = __float2bfloat16(v1);
        __nv_bfloat16 l0 = __float2bfloat16(v0 - __bfloat162float(h0));
        __nv_bfloat16 l1 = __float2bfloat16(v1 - __bfloat162float(h1));
        g_Whi[n * 64 + kp] = (uint32_t)__bfloat16_as_ushort(h0) |
                             ((uint32_t)__bfloat16_as_ushort(h1) << 16);
        g_Wlo[n * 64 + kp] = (uint32_t)__bfloat16_as_ushort(l0) |
                             ((uint32_t)__bfloat16_as_ushort(l1) << 16);
    }
}

__global__ void hist_kernel(const void* __restrict__ ei) {
    int e = blockIdx.x * blockDim.x + threadIdx.x;
    if (e >= N_EDGES) return;
    int c = (int)edge_at(ei, (long long)N_EDGES + e);
    atomicAdd(&g_degi[c], 1);
}

// ---------------------------------------------------------------------------
// Single-pass exclusive scan (decoupled lookback). 98 blocks, all co-resident
// on 148 SMs -> spin-wait is deadlock-free. Status word: flag(hi32) | val(lo32),
// flag 1 = aggregate ready, 2 = inclusive prefix ready.
// Also computes dis = rsqrt(deg+1) and initializes g_cur.
// ---------------------------------------------------------------------------
__global__ __launch_bounds__(SCAN_BLK) void scan_kernel() {
    __shared__ int sh[SCAN_BLK];
    __shared__ int s_pref;
    const int bid = blockIdx.x;
    const int tid = threadIdx.x;
    int i = bid * SCAN_BLK + tid;
    int v = (i < N_NODES) ? g_degi[i] : 0;
    if (i < N_NODES) g_dis[i] = rsqrtf((float)v + 1.0f);
    sh[tid] = v;
    __syncthreads();
    #pragma unroll
    for (int off = 1; off < SCAN_BLK; off <<= 1) {
        int t = (tid >= off) ? sh[tid - off] : 0;
        __syncthreads();
        sh[tid] += t;
        __syncthreads();
    }
    int incl = sh[tid];                       // inclusive within block
    if (tid == 0) {
        int total = sh[SCAN_BLK - 1];
        if (bid == 0) {
            atomicExch(&g_sstat[0], (2ULL << 32) | (unsigned)total);
            s_pref = 0;
        } else {
            atomicExch(&g_sstat[bid], (1ULL << 32) | (unsigned)total);
            int pref = 0;
            int j = bid - 1;
            while (true) {
                unsigned long long s;
                do { s = atomicAdd(&g_sstat[j], 0ULL); } while ((s >> 32) == 0ULL);
                pref += (int)(unsigned)s;
                if ((s >> 32) == 2ULL) break;
                j--;
            }
            atomicExch(&g_sstat[bid], (2ULL << 32) | (unsigned)(pref + total));
            s_pref = pref;
        }
    }
    __syncthreads();
    if (i >= N_NODES) return;
    int base = s_pref + incl - v;             // global exclusive
    g_base[i] = base;
    g_cur[i]  = base;
}

// ---------------------------------------------------------------------------
// Fused GEMM + fill (bf16 3-term split mma.sync.m16n8k16, fp16 output).
// ---------------------------------------------------------------------------
#define XSP 36   // x tile row stride in uint32
#define WSP 68   // W row stride in uint32
#define GEMM_SMEM ((2 * 128 * XSP + 2 * 128 * WSP) * 4)   // 106496 bytes

__device__ __forceinline__ void mma_bf16(float c[4], const uint32_t a[4],
                                         const uint32_t b[2]) {
    asm volatile(
        "mma.sync.aligned.m16n8k16.row.col.f32.bf16.bf16.f32 "
        "{%0,%1,%2,%3}, {%4,%5,%6,%7}, {%8,%9}, {%0,%1,%2,%3};"
        : "+f"(c[0]), "+f"(c[1]), "+f"(c[2]), "+f"(c[3])
        : "r"(a[0]), "r"(a[1]), "r"(a[2]), "r"(a[3]), "r"(b[0]), "r"(b[1]));
}

__global__ __launch_bounds__(256) void gemm_fill_kernel(
    const float* __restrict__ x, const void* __restrict__ ei)
{
    if (blockIdx.x >= G_GEMM) {
        long long start = (long long)(blockIdx.x - G_GEMM) * blockDim.x + threadIdx.x;
        for (long long e = start; e < N_EDGES; e += (long long)G_FILL * 256) {
            int r = (int)edge_at(ei, e);
            int c = (int)edge_at(ei, (long long)N_EDGES + e);
            int pos = atomicAdd(&g_cur[c], 1);
            g_src[pos] = r;
        }
        return;
    }

    extern __shared__ uint32_t smem[];
    uint32_t* xs_hi = smem;                    // [128][XSP]
    uint32_t* xs_lo = xs_hi + 128 * XSP;
    uint32_t* ws_hi = xs_lo + 128 * XSP;       // [128][WSP]
    uint32_t* ws_lo = ws_hi + 128 * WSP;

    const int tid  = threadIdx.x;
    const int lane = tid & 31;
    const int w    = tid >> 5;
    const int wm   = w & 3;
    const int wn   = w >> 2;
    const int grp  = lane >> 2;
    const int qid  = lane & 3;
    const int row0 = blockIdx.x * 128;

    {
        int r = tid >> 1;
        int h = tid & 1;
        const uint4* sh = (const uint4*)&g_Whi[r * 64 + h * 32];
        const uint4* sl = (const uint4*)&g_Wlo[r * 64 + h * 32];
        uint4* dh = (uint4*)&ws_hi[r * WSP + h * 32];
        uint4* dl = (uint4*)&ws_lo[r * WSP + h * 32];
        #pragma unroll
        for (int i = 0; i < 8; i++) { dh[i] = sh[i]; dl[i] = sl[i]; }
    }

    float acc[2][8][4];
    #pragma unroll
    for (int mt = 0; mt < 2; mt++)
        #pragma unroll
        for (int nt = 0; nt < 8; nt++)
            #pragma unroll
            for (int q = 0; q < 4; q++) acc[mt][nt][q] = 0.0f;

    for (int kc = 0; kc < 4; kc++) {            // K chunk = 32
        #pragma unroll
        for (int i = 0; i < 4; i++) {
            int idx = tid + i * 256;
            int r   = idx >> 3;
            int c4  = idx & 7;
            int gr  = row0 + r;
            float4 v = make_float4(0.f, 0.f, 0.f, 0.f);
            if (gr < N_NODES)
                v = *(const float4*)(x + (size_t)gr * FEAT + kc * 32 + c4 * 4);
            const float vv[4] = {v.x, v.y, v.z, v.w};
            #pragma unroll
            for (int j = 0; j < 2; j++) {
                float a0 = vv[2 * j], a1 = vv[2 * j + 1];
                __nv_bfloat16 h0 = __float2bfloat16(a0);
                __nv_bfloat16 h1 = __float2bfloat16(a1);
                __nv_bfloat16 l0 = __float2bfloat16(a0 - __bfloat162float(h0));
                __nv_bfloat16 l1 = __float2bfloat16(a1 - __bfloat162float(h1));
                xs_hi[r * XSP + c4 * 2 + j] =
                    (uint32_t)__bfloat16_as_ushort(h0) |
                    ((uint32_t)__bfloat16_as_ushort(h1) << 16);
                xs_lo[r * XSP + c4 * 2 + j] =
                    (uint32_t)__bfloat16_as_ushort(l0) |
                    ((uint32_t)__bfloat16_as_ushort(l1) << 16);
            }
        }
        __syncthreads();

        #pragma unroll
        for (int ks = 0; ks < 2; ks++) {
            int xp = ks * 8;
            int wp = kc * 16 + ks * 8;
            uint32_t a_hi[2][4], a_lo[2][4];
            #pragma unroll
            for (int mt = 0; mt < 2; mt++) {
                int r0 = 32 * wm + 16 * mt;
                int i0 = (r0 + grp) * XSP + xp + qid;
                int i1 = (r0 + grp + 8) * XSP + xp + qid;
                a_hi[mt][0] = xs_hi[i0];
                a_hi[mt][1] = xs_hi[i1];
                a_hi[mt][2] = xs_hi[i0 + 4];
                a_hi[mt][3] = xs_hi[i1 + 4];
                a_lo[mt][0] = xs_lo[i0];
                a_lo[mt][1] = xs_lo[i1];
                a_lo[mt][2] = xs_lo[i0 + 4];
                a_lo[mt][3] = xs_lo[i1 + 4];
            }
            #pragma unroll
            for (int nt = 0; nt < 8; nt++) {
                int nb = (64 * wn + 8 * nt + grp) * WSP + wp + qid;
                uint32_t b_hi[2], b_lo[2];
                b_hi[0] = ws_hi[nb];
                b_hi[1] = ws_hi[nb + 4];
                b_lo[0] = ws_lo[nb];
                b_lo[1] = ws_lo[nb + 4];
                #pragma unroll
                for (int mt = 0; mt < 2; mt++) {
                    mma_bf16(acc[mt][nt], a_lo[mt], b_hi);
                    mma_bf16(acc[mt][nt], a_hi[mt], b_lo);
                    mma_bf16(acc[mt][nt], a_hi[mt], b_hi);
                }
            }
        }
        __syncthreads();
    }

    #pragma unroll
    for (int mt = 0; mt < 2; mt++) {
        int r0 = row0 + 32 * wm + 16 * mt + grp;
        #pragma unroll
        for (int nt = 0; nt < 8; nt++) {
            int cb = 64 * wn + 8 * nt + 2 * qid;
            if (r0 < N_NODES)
                *(__half2*)(g_xw + (size_t)r0 * FEAT + cb) =
                    __floats2half2_rn(acc[mt][nt][0], acc[mt][nt][1]);
            if (r0 + 8 < N_NODES)
                *(__half2*)(g_xw + (size_t)(r0 + 8) * FEAT + cb) =
                    __floats2half2_rn(acc[mt][nt][2], acc[mt][nt][3]);
        }
    }
}

// ---------------------------------------------------------------------------
// Gather: one warp per target node. Each warp-half (16 lanes x 16B) gathers a
// full fp16 row of one edge -> two edges in flight per iteration, pairs
// unrolled x2 (4 edges in flight). fp32 accum, cross-half shfl reduction.
// ---------------------------------------------------------------------------
__device__ __forceinline__ void accum_row(float acc[8], int r, float n, int fl) {
    uint4 u = *(const uint4*)(g_xw + (size_t)r * FEAT + fl * 8);
    const uint32_t uu[4] = {u.x, u.y, u.z, u.w};
    #pragma unroll
    for (int j = 0; j < 4; j++) {
        float2 f = __half22float2(*reinterpret_cast<const __half2*>(&uu[j]));
        acc[2 * j]     = fmaf(f.x, n, acc[2 * j]);
        acc[2 * j + 1] = fmaf(f.y, n, acc[2 * j + 1]);
    }
}

__global__ __launch_bounds__(256) void gather_kernel(
    const float* __restrict__ b, float* __restrict__ out)
{
    int node = blockIdx.x * 8 + (threadIdx.x >> 5);
    if (node >= N_NODES) return;
    int lane = threadIdx.x & 31;
    int half = lane >> 4;       // 0/1: which edge of the pair
    int fl   = lane & 15;       // feature slice: features [8*fl, 8*fl+8)

    float dc = g_dis[node];

    float acc[8];
    #pragma unroll
    for (int j = 0; j < 8; j++) acc[j] = 0.0f;

    // Self-loop: half 0 accumulates row(node) * dis^2 (half 1 contributes 0).
    if (half == 0) accum_row(acc, node, dc * dc, fl);

    int base = g_base[node];
    int deg  = g_degi[node];

    int i = 0;
    for (; i + 3 < deg; i += 4) {             // 2 pairs in flight
        int e0 = base + i + half;
        int e1 = base + i + 2 + half;
        int r0 = g_src[e0];
        int r1 = g_src[e1];
        float n0 = g_dis[r0] * dc;
        float n1 = g_dis[r1] * dc;
        accum_row(acc, r0, n0, fl);
        accum_row(acc, r1, n1, fl);
    }
    for (; i < deg; i += 2) {
        int idx = i + half;
        if (idx < deg) {
            int r0 = g_src[base + idx];
            accum_row(acc, r0, g_dis[r0] * dc, fl);
        }
    }

    // Cross-half reduction: lanes l and l+16 hold partial sums of slice fl.
    #pragma unroll
    for (int j = 0; j < 8; j++)
        acc[j] += __shfl_xor_sync(0xffffffffu, acc[j], 16);

    // Store: lane writes features [8*fl + 4*half, +4) with bias.
    int fo = 8 * fl + 4 * half;
    float4 bb = *(const float4*)(b + fo);
    float4 o;
    o.x = acc[4 * half + 0] + bb.x;
    o.y = acc[4 * half + 1] + bb.y;
    o.z = acc[4 * half + 2] + bb.z;
    o.w = acc[4 * half + 3] + bb.w;
    *(float4*)(out + (size_t)node * FEAT + fo) = o;
}

// ---------------------------------------------------------------------------
extern "C" void kernel_launch(void* const* d_in, const int* in_sizes, int n_in,
                              void* d_out, int out_size)
{
    const float* x  = (const float*)d_in[0];
    const float* W  = (const float*)d_in[1];
    const float* b  = (const float*)d_in[2];
    const void*  ei = d_in[3];
    float* out = (float*)d_out;

    cudaFuncSetAttribute(gemm_fill_kernel,
                         cudaFuncAttributeMaxDynamicSharedMemorySize, GEMM_SMEM);

    init_wprep_kernel<<<391 + 32, 256>>>((const unsigned int*)ei, W);
    hist_kernel<<<(N_EDGES + 255) / 256, 256>>>(ei);
    scan_kernel<<<N_SBLK, SCAN_BLK>>>();
    gemm_fill_kernel<<<G_GEMM + G_FILL, 256, GEMM_SMEM>>>(x, ei);
    gather_kernel<<<(N_NODES + 7) / 8, 256>>>(b, out);
}

// round 9
// speedup vs baseline: 1.1003x; 1.1003x over previous
#include <cuda_runtime.h>
#include <cuda_bf16.h>
#include <cuda_fp16.h>
#include <cstdint>

#define N_NODES 100000
#define N_EDGES 1600000
#define FEAT 128
#define SCAN_BLK 1024
#define N_SBLK ((N_NODES + SCAN_BLK - 1) / SCAN_BLK)   // 98

#define G_GEMM ((N_NODES + 127) / 128)                 // 782 gemm tile blocks
#define G_FILL 1266                                    // fill blocks in fused grid

// Scratch (static device globals — no allocation).
__device__ __half g_xw[(size_t)N_NODES * FEAT];  // 25.6 MB (fp16 xw)
__device__ float g_dis[N_NODES];
__device__ int   g_degi[N_NODES];
__device__ int   g_base[N_NODES];
__device__ int   g_cur[N_NODES];
__device__ unsigned long long g_sstat[N_SBLK];   // decoupled-lookback status
__device__ int   g_src[N_EDGES];
__device__ int   g_is64;
// W transposed to [n][k], split to fp16 hi/lo, k-pairs packed in uint32.
__device__ uint32_t g_Whi[128 * 64];
__device__ uint32_t g_Wlo[128 * 64];

// ---------------------------------------------------------------------------
__device__ __forceinline__ long long edge_at(const void* p, long long i) {
    if (g_is64) return ((const long long*)p)[i];
    return (long long)((const int*)p)[i];
}

// Fused: blocks [0,391) zero degi + scan status (+detect int64 in block 0);
//        blocks [391,423) transpose/split W into fp16 hi/lo packed images.
__global__ void init_wprep_kernel(const unsigned int* __restrict__ w,
                                  const float* __restrict__ W) {
    if (blockIdx.x < 391) {
        int i = blockIdx.x * blockDim.x + threadIdx.x;
        if (i < N_NODES) g_degi[i] = 0;
        if (i < N_SBLK) g_sstat[i] = 0ULL;
        if (blockIdx.x == 0 && threadIdx.x == 0) {
            int is64 = 1;
            for (int k = 0; k < 64; k++)
                if (w[2 * k + 1] != 0u) { is64 = 0; break; }
            g_is64 = is64;
        }
    } else {
        int idx = (blockIdx.x - 391) * blockDim.x + threadIdx.x;  // 0..8191
        if (idx >= 8192) return;
        int n  = idx >> 6;
        int kp = idx & 63;
        float v0 = W[(size_t)(2 * kp) * FEAT + n];
        float v1 = W[(size_t)(2 * kp + 1) * FEAT + n];
        __half h0 = __float2half_rn(v0);
        __half h1 = __float2half_rn(v1);
        __half l0 = __float2half_rn(v0 - __half2float(h0));
        __half l1 = __float2half_rn(v1 - __half2float(h1));
        g_Whi[n * 64 + kp] = (uint32_t)__half_as_ushort(h0) |
                             ((uint32_t)__half_as_ushort(h1) << 16);
        g_Wlo[n * 64 + kp] = (uint32_t)__half_as_ushort(l0) |
                             ((uint32_t)__half_as_ushort(l1) << 16);
    }
}

__global__ void hist_kernel(const void* __restrict__ ei) {
    int e = blockIdx.x * blockDim.x + threadIdx.x;
    if (e >= N_EDGES) return;
    int c = (int)edge_at(ei, (long long)N_EDGES + e);
    atomicAdd(&g_degi[c], 1);
}

// ---------------------------------------------------------------------------
// Single-pass exclusive scan (decoupled lookback); also dis = rsqrt(deg+1).
// ---------------------------------------------------------------------------
__global__ __launch_bounds__(SCAN_BLK) void scan_kernel() {
    __shared__ int sh[SCAN_BLK];
    __shared__ int s_pref;
    const int bid = blockIdx.x;
    const int tid = threadIdx.x;
    int i = bid * SCAN_BLK + tid;
    int v = (i < N_NODES) ? g_degi[i] : 0;
    if (i < N_NODES) g_dis[i] = rsqrtf((float)v + 1.0f);
    sh[tid] = v;
    __syncthreads();
    #pragma unroll
    for (int off = 1; off < SCAN_BLK; off <<= 1) {
        int t = (tid >= off) ? sh[tid - off] : 0;
        __syncthreads();
        sh[tid] += t;
        __syncthreads();
    }
    int incl = sh[tid];
    if (tid == 0) {
        int total = sh[SCAN_BLK - 1];
        if (bid == 0) {
            atomicExch(&g_sstat[0], (2ULL << 32) | (unsigned)total);
            s_pref = 0;
        } else {
            atomicExch(&g_sstat[bid], (1ULL << 32) | (unsigned)total);
            int pref = 0;
            int j = bid - 1;
            while (true) {
                unsigned long long s;
                do { s = atomicAdd(&g_sstat[j], 0ULL); } while ((s >> 32) == 0ULL);
                pref += (int)(unsigned)s;
                if ((s >> 32) == 2ULL) break;
                j--;
            }
            atomicExch(&g_sstat[bid], (2ULL << 32) | (unsigned)(pref + total));
            s_pref = pref;
        }
    }
    __syncthreads();
    if (i >= N_NODES) return;
    int base = s_pref + incl - v;
    g_base[i] = base;
    g_cur[i]  = base;
}

// ---------------------------------------------------------------------------
// Fused GEMM + fill. GEMM: fp16 asymmetric split, 2 terms:
//   xw ~= fp16(x) * W_hi + fp16(x) * W_lo   (W_hi+W_lo == W exactly to fp32)
// mma.sync.m16n8k16.f16, term-outer scheduling (16 independent mmas/group).
// ---------------------------------------------------------------------------
#define XSP 20   // x tile row stride in uint32 (16 pairs + 4 pad)
#define WSP 68   // W row stride in uint32 (64 pairs + 4 pad)
#define GEMM_SMEM ((128 * XSP + 2 * 128 * WSP) * 4)   // 79872 bytes

__device__ __forceinline__ void mma_f16(float c[4], const uint32_t a[4],
                                        const uint32_t b[2]) {
    asm volatile(
        "mma.sync.aligned.m16n8k16.row.col.f32.f16.f16.f32 "
        "{%0,%1,%2,%3}, {%4,%5,%6,%7}, {%8,%9}, {%0,%1,%2,%3};"
        : "+f"(c[0]), "+f"(c[1]), "+f"(c[2]), "+f"(c[3])
        : "r"(a[0]), "r"(a[1]), "r"(a[2]), "r"(a[3]), "r"(b[0]), "r"(b[1]));
}

__global__ __launch_bounds__(256) void gemm_fill_kernel(
    const float* __restrict__ x, const void* __restrict__ ei)
{
    if (blockIdx.x >= G_GEMM) {
        long long start = (long long)(blockIdx.x - G_GEMM) * blockDim.x + threadIdx.x;
        for (long long e = start; e < N_EDGES; e += (long long)G_FILL * 256) {
            int r = (int)edge_at(ei, e);
            int c = (int)edge_at(ei, (long long)N_EDGES + e);
            int pos = atomicAdd(&g_cur[c], 1);
            g_src[pos] = r;
        }
        return;
    }

    extern __shared__ uint32_t smem[];
    uint32_t* xs    = smem;                    // [128][XSP] fp16 pairs
    uint32_t* ws_hi = xs + 128 * XSP;          // [128][WSP]
    uint32_t* ws_lo = ws_hi + 128 * WSP;

    const int tid  = threadIdx.x;
    const int lane = tid & 31;
    const int w    = tid >> 5;
    const int wm   = w & 3;
    const int wn   = w >> 2;
    const int grp  = lane >> 2;
    const int qid  = lane & 3;
    const int row0 = blockIdx.x * 128;

    // Copy precomputed W images (L2-resident) into padded SMEM.
    {
        int r = tid >> 1;
        int h = tid & 1;
        const uint4* sh = (const uint4*)&g_Whi[r * 64 + h * 32];
        const uint4* sl = (const uint4*)&g_Wlo[r * 64 + h * 32];
        uint4* dh = (uint4*)&ws_hi[r * WSP + h * 32];
        uint4* dl = (uint4*)&ws_lo[r * WSP + h * 32];
        #pragma unroll
        for (int i = 0; i < 8; i++) { dh[i] = sh[i]; dl[i] = sl[i]; }
    }

    float acc[2][8][4];
    #pragma unroll
    for (int mt = 0; mt < 2; mt++)
        #pragma unroll
        for (int nt = 0; nt < 8; nt++)
            #pragma unroll
            for (int q = 0; q < 4; q++) acc[mt][nt][q] = 0.0f;

    for (int kc = 0; kc < 4; kc++) {            // K chunk = 32
        // Load x chunk as fp16 pairs: 128 rows x 16 pairs.
        #pragma unroll
        for (int i = 0; i < 4; i++) {
            int idx = tid + i * 256;
            int r   = idx >> 3;
            int c4  = idx & 7;
            int gr  = row0 + r;
            float4 v = make_float4(0.f, 0.f, 0.f, 0.f);
            if (gr < N_NODES)
                v = *(const float4*)(x + (size_t)gr * FEAT + kc * 32 + c4 * 4);
            __half2 p0 = __float22half2_rn(make_float2(v.x, v.y));
            __half2 p1 = __float22half2_rn(make_float2(v.z, v.w));
            xs[r * XSP + c4 * 2 + 0] = *reinterpret_cast<uint32_t*>(&p0);
            xs[r * XSP + c4 * 2 + 1] = *reinterpret_cast<uint32_t*>(&p1);
        }
        __syncthreads();

        #pragma unroll
        for (int ks = 0; ks < 2; ks++) {        // two K=16 steps per chunk
            int xp = ks * 8;
            int wp = kc * 16 + ks * 8;

            uint32_t a[2][4];
            #pragma unroll
            for (int mt = 0; mt < 2; mt++) {
                int r0 = 32 * wm + 16 * mt;
                int i0 = (r0 + grp) * XSP + xp + qid;
                int i1 = (r0 + grp + 8) * XSP + xp + qid;
                a[mt][0] = xs[i0];
                a[mt][1] = xs[i1];
                a[mt][2] = xs[i0 + 4];
                a[mt][3] = xs[i1 + 4];
            }

            // Term 1: W_hi — 16 independent mmas.
            uint32_t b[8][2];
            #pragma unroll
            for (int nt = 0; nt < 8; nt++) {
                int nb = (64 * wn + 8 * nt + grp) * WSP + wp + qid;
                b[nt][0] = ws_hi[nb];
                b[nt][1] = ws_hi[nb + 4];
            }
            #pragma unroll
            for (int nt = 0; nt < 8; nt++) {
                mma_f16(acc[0][nt], a[0], b[nt]);
                mma_f16(acc[1][nt], a[1], b[nt]);
            }

            // Term 2: W_lo — 16 independent mmas.
            #pragma unroll
            for (int nt = 0; nt < 8; nt++) {
                int nb = (64 * wn + 8 * nt + grp) * WSP + wp + qid;
                b[nt][0] = ws_lo[nb];
                b[nt][1] = ws_lo[nb + 4];
            }
            #pragma unroll
            for (int nt = 0; nt < 8; nt++) {
                mma_f16(acc[0][nt], a[0], b[nt]);
                mma_f16(acc[1][nt], a[1], b[nt]);
            }
        }
        __syncthreads();
    }

    // Epilogue: write fp16 xw.
    #pragma unroll
    for (int mt = 0; mt < 2; mt++) {
        int r0 = row0 + 32 * wm + 16 * mt + grp;
        #pragma unroll
        for (int nt = 0; nt < 8; nt++) {
            int cb = 64 * wn + 8 * nt + 2 * qid;
            if (r0 < N_NODES)
                *(__half2*)(g_xw + (size_t)r0 * FEAT + cb) =
                    __floats2half2_rn(acc[mt][nt][0], acc[mt][nt][1]);
            if (r0 + 8 < N_NODES)
                *(__half2*)(g_xw + (size_t)(r0 + 8) * FEAT + cb) =
                    __floats2half2_rn(acc[mt][nt][2], acc[mt][nt][3]);
        }
    }
}

// ---------------------------------------------------------------------------
// Gather: one warp per target node; fp16 row reads (8B/lane), fp32 accum.
// ---------------------------------------------------------------------------
__device__ __forceinline__ float4 load_row4(long long node, int lane) {
    uint2 u = *((const uint2*)(g_xw + (size_t)node * FEAT) + lane);
    __half2 p0 = *reinterpret_cast<__half2*>(&u.x);
    __half2 p1 = *reinterpret_cast<__half2*>(&u.y);
    float2 f0 = __half22float2(p0);
    float2 f1 = __half22float2(p1);
    return make_float4(f0.x, f0.y, f1.x, f1.y);
}

__global__ __launch_bounds__(256) void gather_kernel(
    const float* __restrict__ b, float* __restrict__ out)
{
    int node = blockIdx.x * 8 + (threadIdx.x >> 5);
    if (node >= N_NODES) return;
    int lane = threadIdx.x & 31;

    float dc = g_dis[node];
    float d2 = dc * dc;

    float4 acc = load_row4(node, lane);
    acc.x *= d2; acc.y *= d2; acc.z *= d2; acc.w *= d2;   // self-loop

    int base = g_base[node];
    int deg  = g_degi[node];

    int i = 0;
    for (; i + 1 < deg; i += 2) {
        int r0 = g_src[base + i];
        int r1 = g_src[base + i + 1];
        float n0 = g_dis[r0] * dc;
        float n1 = g_dis[r1] * dc;
        float4 v0 = load_row4(r0, lane);
        float4 v1 = load_row4(r1, lane);
        acc.x = fmaf(v0.x, n0, acc.x); acc.y = fmaf(v0.y, n0, acc.y);
        acc.z = fmaf(v0.z, n0, acc.z); acc.w = fmaf(v0.w, n0, acc.w);
        acc.x = fmaf(v1.x, n1, acc.x); acc.y = fmaf(v1.y, n1, acc.y);
        acc.z = fmaf(v1.z, n1, acc.z); acc.w = fmaf(v1.w, n1, acc.w);
    }
    if (i < deg) {
        int r0 = g_src[base + i];
        float n0 = g_dis[r0] * dc;
        float4 v0 = load_row4(r0, lane);
        acc.x = fmaf(v0.x, n0, acc.x); acc.y = fmaf(v0.y, n0, acc.y);
        acc.z = fmaf(v0.z, n0, acc.z); acc.w = fmaf(v0.w, n0, acc.w);
    }

    float4 bb = ((const float4*)b)[lane];
    acc.x += bb.x; acc.y += bb.y; acc.z += bb.z; acc.w += bb.w;
    ((float4*)(out + (size_t)node * FEAT))[lane] = acc;
}

// ---------------------------------------------------------------------------
extern "C" void kernel_launch(void* const* d_in, const int* in_sizes, int n_in,
                              void* d_out, int out_size)
{
    const float* x  = (const float*)d_in[0];
    const float* W  = (const float*)d_in[1];
    const float* b  = (const float*)d_in[2];
    const void*  ei = d_in[3];
    float* out = (float*)d_out;

    cudaFuncSetAttribute(gemm_fill_kernel,
                         cudaFuncAttributeMaxDynamicSharedMemorySize, GEMM_SMEM);

    init_wprep_kernel<<<391 + 32, 256>>>((const unsigned int*)ei, W);
    hist_kernel<<<(N_EDGES + 255) / 256, 256>>>(ei);
    scan_kernel<<<N_SBLK, SCAN_BLK>>>();
    gemm_fill_kernel<<<G_GEMM + G_FILL, 256, GEMM_SMEM>>>(x, ei);
    gather_kernel<<<(N_NODES + 7) / 8, 256>>>(b, out);
}

// round 10
// speedup vs baseline: 1.1468x; 1.0423x over previous
#include <cuda_runtime.h>
#include <cuda_bf16.h>
#include <cuda_fp16.h>
#include <cstdint>

#define N_NODES 100000
#define N_EDGES 1600000
#define FEAT 128
#define SCAN_BLK 1024
#define N_SBLK ((N_NODES + SCAN_BLK - 1) / SCAN_BLK)   // 98

#define G_GEMM ((N_NODES + 127) / 128)                 // 782 gemm tile blocks
#define G_FILL 1266                                    // fill blocks in fused grid

// Scratch (static device globals — no allocation).
__device__ __half g_xw[(size_t)N_NODES * FEAT];  // 25.6 MB (fp16 xw)
__device__ float g_dis[N_NODES];
__device__ int   g_degi[N_NODES];
__device__ int   g_base[N_NODES];
__device__ int   g_cur[N_NODES];
__device__ unsigned long long g_sstat[N_SBLK];   // decoupled-lookback status
__device__ int   g_src[N_EDGES];
__device__ int   g_is64;
// W transposed to [n][k] fp16, k-pairs packed in uint32.
__device__ uint32_t g_Wimg[128 * 64];

// ---------------------------------------------------------------------------
__device__ __forceinline__ long long edge_at(const void* p, long long i) {
    if (g_is64) return ((const long long*)p)[i];
    return (long long)((const int*)p)[i];
}

// Fused: blocks [0,391) zero degi + scan status (+detect int64 in block 0);
//        blocks [391,423) transpose W to [n][k] fp16 packed image.
__global__ void init_wprep_kernel(const unsigned int* __restrict__ w,
                                  const float* __restrict__ W) {
    if (blockIdx.x < 391) {
        int i = blockIdx.x * blockDim.x + threadIdx.x;
        if (i < N_NODES) g_degi[i] = 0;
        if (i < N_SBLK) g_sstat[i] = 0ULL;
        if (blockIdx.x == 0 && threadIdx.x == 0) {
            int is64 = 1;
            for (int k = 0; k < 64; k++)
                if (w[2 * k + 1] != 0u) { is64 = 0; break; }
            g_is64 = is64;
        }
    } else {
        int idx = (blockIdx.x - 391) * blockDim.x + threadIdx.x;  // 0..8191
        if (idx >= 8192) return;
        int n  = idx >> 6;
        int kp = idx & 63;
        float v0 = W[(size_t)(2 * kp) * FEAT + n];
        float v1 = W[(size_t)(2 * kp + 1) * FEAT + n];
        __half h0 = __float2half_rn(v0);
        __half h1 = __float2half_rn(v1);
        g_Wimg[n * 64 + kp] = (uint32_t)__half_as_ushort(h0) |
                              ((uint32_t)__half_as_ushort(h1) << 16);
    }
}

__global__ void hist_kernel(const void* __restrict__ ei) {
    int e = blockIdx.x * blockDim.x + threadIdx.x;
    if (e >= N_EDGES) return;
    int c = (int)edge_at(ei, (long long)N_EDGES + e);
    atomicAdd(&g_degi[c], 1);
}

// ---------------------------------------------------------------------------
// Single-pass exclusive scan (decoupled lookback); also dis = rsqrt(deg+1).
// ---------------------------------------------------------------------------
__global__ __launch_bounds__(SCAN_BLK) void scan_kernel() {
    __shared__ int sh[SCAN_BLK];
    __shared__ int s_pref;
    const int bid = blockIdx.x;
    const int tid = threadIdx.x;
    int i = bid * SCAN_BLK + tid;
    int v = (i < N_NODES) ? g_degi[i] : 0;
    if (i < N_NODES) g_dis[i] = rsqrtf((float)v + 1.0f);
    sh[tid] = v;
    __syncthreads();
    #pragma unroll
    for (int off = 1; off < SCAN_BLK; off <<= 1) {
        int t = (tid >= off) ? sh[tid - off] : 0;
        __syncthreads();
        sh[tid] += t;
        __syncthreads();
    }
    int incl = sh[tid];
    if (tid == 0) {
        int total = sh[SCAN_BLK - 1];
        if (bid == 0) {
            atomicExch(&g_sstat[0], (2ULL << 32) | (unsigned)total);
            s_pref = 0;
        } else {
            atomicExch(&g_sstat[bid], (1ULL << 32) | (unsigned)total);
            int pref = 0;
            int j = bid - 1;
            while (true) {
                unsigned long long s;
                do { s = atomicAdd(&g_sstat[j], 0ULL); } while ((s >> 32) == 0ULL);
                pref += (int)(unsigned)s;
                if ((s >> 32) == 2ULL) break;
                j--;
            }
            atomicExch(&g_sstat[bid], (2ULL << 32) | (unsigned)(pref + total));
            s_pref = pref;
        }
    }
    __syncthreads();
    if (i >= N_NODES) return;
    int base = s_pref + incl - v;
    g_base[i] = base;
    g_cur[i]  = base;
}

// ---------------------------------------------------------------------------
// Fused GEMM + fill. GEMM: pure fp16 single term:
//   xw ~= fp16(x) * fp16(W)    (fp32 accumulate)
// mma.sync.m16n8k16.f32.f16.f16.f32, 16 independent mmas per K-step.
// ---------------------------------------------------------------------------
#define XSP 20   // x tile row stride in uint32 (16 pairs + 4 pad)
#define WSP 68   // W row stride in uint32 (64 pairs + 4 pad)
#define GEMM_SMEM ((128 * XSP + 128 * WSP) * 4)   // 45056 bytes

__device__ __forceinline__ void mma_f16(float c[4], const uint32_t a[4],
                                        const uint32_t b[2]) {
    asm volatile(
        "mma.sync.aligned.m16n8k16.row.col.f32.f16.f16.f32 "
        "{%0,%1,%2,%3}, {%4,%5,%6,%7}, {%8,%9}, {%0,%1,%2,%3};"
        : "+f"(c[0]), "+f"(c[1]), "+f"(c[2]), "+f"(c[3])
        : "r"(a[0]), "r"(a[1]), "r"(a[2]), "r"(a[3]), "r"(b[0]), "r"(b[1]));
}

__global__ __launch_bounds__(256) void gemm_fill_kernel(
    const float* __restrict__ x, const void* __restrict__ ei)
{
    if (blockIdx.x >= G_GEMM) {
        long long start = (long long)(blockIdx.x - G_GEMM) * blockDim.x + threadIdx.x;
        for (long long e = start; e < N_EDGES; e += (long long)G_FILL * 256) {
            int r = (int)edge_at(ei, e);
            int c = (int)edge_at(ei, (long long)N_EDGES + e);
            int pos = atomicAdd(&g_cur[c], 1);
            g_src[pos] = r;
        }
        return;
    }

    extern __shared__ uint32_t smem[];
    uint32_t* xs = smem;                       // [128][XSP] fp16 pairs
    uint32_t* ws = xs + 128 * XSP;             // [128][WSP]

    const int tid  = threadIdx.x;
    const int lane = tid & 31;
    const int w    = tid >> 5;
    const int wm   = w & 3;
    const int wn   = w >> 2;
    const int grp  = lane >> 2;
    const int qid  = lane & 3;
    const int row0 = blockIdx.x * 128;

    // Copy precomputed W image (L2-resident) into padded SMEM.
    {
        int r = tid >> 1;
        int h = tid & 1;
        const uint4* s = (const uint4*)&g_Wimg[r * 64 + h * 32];
        uint4* d = (uint4*)&ws[r * WSP + h * 32];
        #pragma unroll
        for (int i = 0; i < 8; i++) d[i] = s[i];
    }

    float acc[2][8][4];
    #pragma unroll
    for (int mt = 0; mt < 2; mt++)
        #pragma unroll
        for (int nt = 0; nt < 8; nt++)
            #pragma unroll
            for (int q = 0; q < 4; q++) acc[mt][nt][q] = 0.0f;

    for (int kc = 0; kc < 4; kc++) {            // K chunk = 32
        // Load x chunk as fp16 pairs: 128 rows x 16 pairs.
        #pragma unroll
        for (int i = 0; i < 4; i++) {
            int idx = tid + i * 256;
            int r   = idx >> 3;
            int c4  = idx & 7;
            int gr  = row0 + r;
            float4 v = make_float4(0.f, 0.f, 0.f, 0.f);
            if (gr < N_NODES)
                v = *(const float4*)(x + (size_t)gr * FEAT + kc * 32 + c4 * 4);
            __half2 p0 = __float22half2_rn(make_float2(v.x, v.y));
            __half2 p1 = __float22half2_rn(make_float2(v.z, v.w));
            xs[r * XSP + c4 * 2 + 0] = *reinterpret_cast<uint32_t*>(&p0);
            xs[r * XSP + c4 * 2 + 1] = *reinterpret_cast<uint32_t*>(&p1);
        }
        __syncthreads();

        #pragma unroll
        for (int ks = 0; ks < 2; ks++) {        // two K=16 steps per chunk
            int xp = ks * 8;
            int wp = kc * 16 + ks * 8;

            uint32_t a[2][4];
            #pragma unroll
            for (int mt = 0; mt < 2; mt++) {
                int r0 = 32 * wm + 16 * mt;
                int i0 = (r0 + grp) * XSP + xp + qid;
                int i1 = (r0 + grp + 8) * XSP + xp + qid;
                a[mt][0] = xs[i0];
                a[mt][1] = xs[i1];
                a[mt][2] = xs[i0 + 4];
                a[mt][3] = xs[i1 + 4];
            }

            uint32_t b[8][2];
            #pragma unroll
            for (int nt = 0; nt < 8; nt++) {
                int nb = (64 * wn + 8 * nt + grp) * WSP + wp + qid;
                b[nt][0] = ws[nb];
                b[nt][1] = ws[nb + 4];
            }
            #pragma unroll
            for (int nt = 0; nt < 8; nt++) {
                mma_f16(acc[0][nt], a[0], b[nt]);
                mma_f16(acc[1][nt], a[1], b[nt]);
            }
        }
        __syncthreads();
    }

    // Epilogue: write fp16 xw.
    #pragma unroll
    for (int mt = 0; mt < 2; mt++) {
        int r0 = row0 + 32 * wm + 16 * mt + grp;
        #pragma unroll
        for (int nt = 0; nt < 8; nt++) {
            int cb = 64 * wn + 8 * nt + 2 * qid;
            if (r0 < N_NODES)
                *(__half2*)(g_xw + (size_t)r0 * FEAT + cb) =
                    __floats2half2_rn(acc[mt][nt][0], acc[mt][nt][1]);
            if (r0 + 8 < N_NODES)
                *(__half2*)(g_xw + (size_t)(r0 + 8) * FEAT + cb) =
                    __floats2half2_rn(acc[mt][nt][2], acc[mt][nt][3]);
        }
    }
}

// ---------------------------------------------------------------------------
// Gather: one warp per target node; fp16 row reads (8B/lane), fp32 accum.
// ---------------------------------------------------------------------------
__device__ __forceinline__ float4 load_row4(long long node, int lane) {
    uint2 u = *((const uint2*)(g_xw + (size_t)node * FEAT) + lane);
    __half2 p0 = *reinterpret_cast<__half2*>(&u.x);
    __half2 p1 = *reinterpret_cast<__half2*>(&u.y);
    float2 f0 = __half22float2(p0);
    float2 f1 = __half22float2(p1);
    return make_float4(f0.x, f0.y, f1.x, f1.y);
}

__global__ __launch_bounds__(256) void gather_kernel(
    const float* __restrict__ b, float* __restrict__ out)
{
    int node = blockIdx.x * 8 + (threadIdx.x >> 5);
    if (node >= N_NODES) return;
    int lane = threadIdx.x & 31;

    float dc = g_dis[node];
    float d2 = dc * dc;

    float4 acc = load_row4(node, lane);
    acc.x *= d2; acc.y *= d2; acc.z *= d2; acc.w *= d2;   // self-loop

    int base = g_base[node];
    int deg  = g_degi[node];

    int i = 0;
    for (; i + 1 < deg; i += 2) {
        int r0 = g_src[base + i];
        int r1 = g_src[base + i + 1];
        float n0 = g_dis[r0] * dc;
        float n1 = g_dis[r1] * dc;
        float4 v0 = load_row4(r0, lane);
        float4 v1 = load_row4(r1, lane);
        acc.x = fmaf(v0.x, n0, acc.x); acc.y = fmaf(v0.y, n0, acc.y);
        acc.z = fmaf(v0.z, n0, acc.z); acc.w = fmaf(v0.w, n0, acc.w);
        acc.x = fmaf(v1.x, n1, acc.x); acc.y = fmaf(v1.y, n1, acc.y);
        acc.z = fmaf(v1.z, n1, acc.z); acc.w = fmaf(v1.w, n1, acc.w);
    }
    if (i < deg) {
        int r0 = g_src[base + i];
        float n0 = g_dis[r0] * dc;
        float4 v0 = load_row4(r0, lane);
        acc.x = fmaf(v0.x, n0, acc.x); acc.y = fmaf(v0.y, n0, acc.y);
        acc.z = fmaf(v0.z, n0, acc.z); acc.w = fmaf(v0.w, n0, acc.w);
    }

    float4 bb = ((const float4*)b)[lane];
    acc.x += bb.x; acc.y += bb.y; acc.z += bb.z; acc.w += bb.w;
    ((float4*)(out + (size_t)node * FEAT))[lane] = acc;
}

// ---------------------------------------------------------------------------
extern "C" void kernel_launch(void* const* d_in, const int* in_sizes, int n_in,
                              void* d_out, int out_size)
{
    const float* x  = (const float*)d_in[0];
    const float* W  = (const float*)d_in[1];
    const float* b  = (const float*)d_in[2];
    const void*  ei = d_in[3];
    float* out = (float*)d_out;

    cudaFuncSetAttribute(gemm_fill_kernel,
                         cudaFuncAttributeMaxDynamicSharedMemorySize, GEMM_SMEM);

    init_wprep_kernel<<<391 + 32, 256>>>((const unsigned int*)ei, W);
    hist_kernel<<<(N_EDGES + 255) / 256, 256>>>(ei);
    scan_kernel<<<N_SBLK, SCAN_BLK>>>();
    gemm_fill_kernel<<<G_GEMM + G_FILL, 256, GEMM_SMEM>>>(x, ei);
    gather_kernel<<<(N_NODES + 7) / 8, 256>>>(b, out);
}

// round 11
// speedup vs baseline: 1.2332x; 1.0753x over previous
#include <cuda_runtime.h>
#include <cuda_bf16.h>
#include <cuda_fp16.h>
#include <cstdint>

#define N_NODES 100000
#define N_EDGES 1600000
#define FEAT 128
#define SCAN_BLK 1024
#define N_SBLK ((N_NODES + SCAN_BLK - 1) / SCAN_BLK)   // 98

#define G_GEMM ((N_NODES + 127) / 128)                 // 782 gemm tile blocks
#define G_FILL 1266                                    // fill blocks in fused grid

// Scratch (static device globals — no allocation).
__device__ __half g_xw[(size_t)N_NODES * FEAT];  // 25.6 MB (fp16 xw)
__device__ float g_dis[N_NODES];
__device__ int   g_degi[N_NODES];
__device__ int   g_base[N_NODES];
__device__ int   g_cur[N_NODES];
__device__ unsigned long long g_sstat[N_SBLK];   // decoupled-lookback status
__device__ int   g_src[N_EDGES];
__device__ int   g_is64;
// W transposed to [n][k] fp16, k-pairs packed in uint32.
__device__ uint32_t g_Wimg[128 * 64];

// ---------------------------------------------------------------------------
__device__ __forceinline__ long long edge_at(const void* p, long long i) {
    if (g_is64) return ((const long long*)p)[i];
    return (long long)((const int*)p)[i];
}

// Fused: blocks [0,391) zero degi + scan status (+detect int64 in block 0);
//        blocks [391,423) transpose W to [n][k] fp16 packed image.
__global__ void init_wprep_kernel(const unsigned int* __restrict__ w,
                                  const float* __restrict__ W) {
    if (blockIdx.x < 391) {
        int i = blockIdx.x * blockDim.x + threadIdx.x;
        if (i < N_NODES) g_degi[i] = 0;
        if (i < N_SBLK) g_sstat[i] = 0ULL;
        if (blockIdx.x == 0 && threadIdx.x == 0) {
            int is64 = 1;
            for (int k = 0; k < 64; k++)
                if (w[2 * k + 1] != 0u) { is64 = 0; break; }
            g_is64 = is64;
        }
    } else {
        int idx = (blockIdx.x - 391) * blockDim.x + threadIdx.x;  // 0..8191
        if (idx >= 8192) return;
        int n  = idx >> 6;
        int kp = idx & 63;
        float v0 = W[(size_t)(2 * kp) * FEAT + n];
        float v1 = W[(size_t)(2 * kp + 1) * FEAT + n];
        __half h0 = __float2half_rn(v0);
        __half h1 = __float2half_rn(v1);
        g_Wimg[n * 64 + kp] = (uint32_t)__half_as_ushort(h0) |
                              ((uint32_t)__half_as_ushort(h1) << 16);
    }
}

__global__ void hist_kernel(const void* __restrict__ ei) {
    int e = blockIdx.x * blockDim.x + threadIdx.x;
    if (e >= N_EDGES) return;
    int c = (int)edge_at(ei, (long long)N_EDGES + e);
    atomicAdd(&g_degi[c], 1);
}

// ---------------------------------------------------------------------------
// Single-pass exclusive scan (decoupled lookback); also dis = rsqrt(deg+1).
// ---------------------------------------------------------------------------
__global__ __launch_bounds__(SCAN_BLK) void scan_kernel() {
    __shared__ int sh[SCAN_BLK];
    __shared__ int s_pref;
    const int bid = blockIdx.x;
    const int tid = threadIdx.x;
    int i = bid * SCAN_BLK + tid;
    int v = (i < N_NODES) ? g_degi[i] : 0;
    if (i < N_NODES) g_dis[i] = rsqrtf((float)v + 1.0f);
    sh[tid] = v;
    __syncthreads();
    #pragma unroll
    for (int off = 1; off < SCAN_BLK; off <<= 1) {
        int t = (tid >= off) ? sh[tid - off] : 0;
        __syncthreads();
        sh[tid] += t;
        __syncthreads();
    }
    int incl = sh[tid];
    if (tid == 0) {
        int total = sh[SCAN_BLK - 1];
        if (bid == 0) {
            atomicExch(&g_sstat[0], (2ULL << 32) | (unsigned)total);
            s_pref = 0;
        } else {
            atomicExch(&g_sstat[bid], (1ULL << 32) | (unsigned)total);
            int pref = 0;
            int j = bid - 1;
            while (true) {
                unsigned long long s;
                do { s = atomicAdd(&g_sstat[j], 0ULL); } while ((s >> 32) == 0ULL);
                pref += (int)(unsigned)s;
                if ((s >> 32) == 2ULL) break;
                j--;
            }
            atomicExch(&g_sstat[bid], (2ULL << 32) | (unsigned)(pref + total));
            s_pref = pref;
        }
    }
    __syncthreads();
    if (i >= N_NODES) return;
    int base = s_pref + incl - v;
    g_base[i] = base;
    g_cur[i]  = base;
}

// ---------------------------------------------------------------------------
// Fused GEMM + fill. GEMM: pure fp16 single term, software-pipelined:
// x chunk k+1 is prefetched into registers before the mma phase of chunk k,
// hiding DRAM latency behind tensor work. fp32 accumulate.
// ---------------------------------------------------------------------------
#define XSP 20   // x tile row stride in uint32 (16 pairs + 4 pad)
#define WSP 68   // W row stride in uint32 (64 pairs + 4 pad)
#define GEMM_SMEM ((128 * XSP + 128 * WSP) * 4)   // 45056 bytes

__device__ __forceinline__ void mma_f16(float c[4], const uint32_t a[4],
                                        const uint32_t b[2]) {
    asm volatile(
        "mma.sync.aligned.m16n8k16.row.col.f32.f16.f16.f32 "
        "{%0,%1,%2,%3}, {%4,%5,%6,%7}, {%8,%9}, {%0,%1,%2,%3};"
        : "+f"(c[0]), "+f"(c[1]), "+f"(c[2]), "+f"(c[3])
        : "r"(a[0]), "r"(a[1]), "r"(a[2]), "r"(a[3]), "r"(b[0]), "r"(b[1]));
}

__global__ __launch_bounds__(256) void gemm_fill_kernel(
    const float* __restrict__ x, const void* __restrict__ ei)
{
    if (blockIdx.x >= G_GEMM) {
        long long start = (long long)(blockIdx.x - G_GEMM) * blockDim.x + threadIdx.x;
        for (long long e = start; e < N_EDGES; e += (long long)G_FILL * 256) {
            int r = (int)edge_at(ei, e);
            int c = (int)edge_at(ei, (long long)N_EDGES + e);
            int pos = atomicAdd(&g_cur[c], 1);
            g_src[pos] = r;
        }
        return;
    }

    extern __shared__ uint32_t smem[];
    uint32_t* xs = smem;                       // [128][XSP] fp16 pairs
    uint32_t* ws = xs + 128 * XSP;             // [128][WSP]

    const int tid  = threadIdx.x;
    const int lane = tid & 31;
    const int w    = tid >> 5;
    const int wm   = w & 3;
    const int wn   = w >> 2;
    const int grp  = lane >> 2;
    const int qid  = lane & 3;
    const int row0 = blockIdx.x * 128;

    // Per-thread x-load coordinates (fixed across chunks).
    const int lr  = tid >> 1;                  // row pair base: handles rows lr, via 4 slots
    // Each thread owns 4 float4 slots: idx = tid + i*256 -> r = idx>>3, c4 = idx&7
    // Prefetch registers for one chunk:
    float4 pre[4];

    // Copy precomputed W image (L2-resident) into padded SMEM.
    {
        int r = tid >> 1;
        int h = tid & 1;
        const uint4* s = (const uint4*)&g_Wimg[r * 64 + h * 32];
        uint4* d = (uint4*)&ws[r * WSP + h * 32];
        #pragma unroll
        for (int i = 0; i < 8; i++) d[i] = s[i];
    }
    (void)lr;

    // Preload chunk 0 into registers.
    #pragma unroll
    for (int i = 0; i < 4; i++) {
        int idx = tid + i * 256;
        int r   = idx >> 3;
        int c4  = idx & 7;
        int gr  = row0 + r;
        pre[i] = make_float4(0.f, 0.f, 0.f, 0.f);
        if (gr < N_NODES)
            pre[i] = *(const float4*)(x + (size_t)gr * FEAT + c4 * 4);
    }

    float acc[2][8][4];
    #pragma unroll
    for (int mt = 0; mt < 2; mt++)
        #pragma unroll
        for (int nt = 0; nt < 8; nt++)
            #pragma unroll
            for (int q = 0; q < 4; q++) acc[mt][nt][q] = 0.0f;

    for (int kc = 0; kc < 4; kc++) {            // K chunk = 32
        // Convert + store the prefetched chunk.
        #pragma unroll
        for (int i = 0; i < 4; i++) {
            int idx = tid + i * 256;
            int r   = idx >> 3;
            int c4  = idx & 7;
            __half2 p0 = __float22half2_rn(make_float2(pre[i].x, pre[i].y));
            __half2 p1 = __float22half2_rn(make_float2(pre[i].z, pre[i].w));
            xs[r * XSP + c4 * 2 + 0] = *reinterpret_cast<uint32_t*>(&p0);
            xs[r * XSP + c4 * 2 + 1] = *reinterpret_cast<uint32_t*>(&p1);
        }
        __syncthreads();

        // Issue next chunk's global loads BEFORE the mma phase (latency hiding).
        if (kc < 3) {
            #pragma unroll
            for (int i = 0; i < 4; i++) {
                int idx = tid + i * 256;
                int r   = idx >> 3;
                int c4  = idx & 7;
                int gr  = row0 + r;
                pre[i] = make_float4(0.f, 0.f, 0.f, 0.f);
                if (gr < N_NODES)
                    pre[i] = *(const float4*)(x + (size_t)gr * FEAT +
                                              (kc + 1) * 32 + c4 * 4);
            }
        }

        #pragma unroll
        for (int ks = 0; ks < 2; ks++) {        // two K=16 steps per chunk
            int xp = ks * 8;
            int wp = kc * 16 + ks * 8;

            uint32_t a[2][4];
            #pragma unroll
            for (int mt = 0; mt < 2; mt++) {
                int r0 = 32 * wm + 16 * mt;
                int i0 = (r0 + grp) * XSP + xp + qid;
                int i1 = (r0 + grp + 8) * XSP + xp + qid;
                a[mt][0] = xs[i0];
                a[mt][1] = xs[i1];
                a[mt][2] = xs[i0 + 4];
                a[mt][3] = xs[i1 + 4];
            }

            uint32_t b[8][2];
            #pragma unroll
            for (int nt = 0; nt < 8; nt++) {
                int nb = (64 * wn + 8 * nt + grp) * WSP + wp + qid;
                b[nt][0] = ws[nb];
                b[nt][1] = ws[nb + 4];
            }
            #pragma unroll
            for (int nt = 0; nt < 8; nt++) {
                mma_f16(acc[0][nt], a[0], b[nt]);
                mma_f16(acc[1][nt], a[1], b[nt]);
            }
        }
        __syncthreads();
    }

    // Epilogue: write fp16 xw.
    #pragma unroll
    for (int mt = 0; mt < 2; mt++) {
        int r0 = row0 + 32 * wm + 16 * mt + grp;
        #pragma unroll
        for (int nt = 0; nt < 8; nt++) {
            int cb = 64 * wn + 8 * nt + 2 * qid;
            if (r0 < N_NODES)
                *(__half2*)(g_xw + (size_t)r0 * FEAT + cb) =
                    __floats2half2_rn(acc[mt][nt][0], acc[mt][nt][1]);
            if (r0 + 8 < N_NODES)
                *(__half2*)(g_xw + (size_t)(r0 + 8) * FEAT + cb) =
                    __floats2half2_rn(acc[mt][nt][2], acc[mt][nt][3]);
        }
    }
}

// ---------------------------------------------------------------------------
// Gather: one warp per target node; fp16 row reads (8B/lane), fp32 accum.
// ---------------------------------------------------------------------------
__device__ __forceinline__ float4 load_row4(long long node, int lane) {
    uint2 u = *((const uint2*)(g_xw + (size_t)node * FEAT) + lane);
    __half2 p0 = *reinterpret_cast<__half2*>(&u.x);
    __half2 p1 = *reinterpret_cast<__half2*>(&u.y);
    float2 f0 = __half22float2(p0);
    float2 f1 = __half22float2(p1);
    return make_float4(f0.x, f0.y, f1.x, f1.y);
}

__global__ __launch_bounds__(256) void gather_kernel(
    const float* __restrict__ b, float* __restrict__ out)
{
    int node = blockIdx.x * 8 + (threadIdx.x >> 5);
    if (node >= N_NODES) return;
    int lane = threadIdx.x & 31;

    float dc = g_dis[node];
    float d2 = dc * dc;

    float4 acc = load_row4(node, lane);
    acc.x *= d2; acc.y *= d2; acc.z *= d2; acc.w *= d2;   // self-loop

    int base = g_base[node];
    int deg  = g_degi[node];

    int i = 0;
    for (; i + 1 < deg; i += 2) {
        int r0 = g_src[base + i];
        int r1 = g_src[base + i + 1];
        float n0 = g_dis[r0] * dc;
        float n1 = g_dis[r1] * dc;
        float4 v0 = load_row4(r0, lane);
        float4 v1 = load_row4(r1, lane);
        acc.x = fmaf(v0.x, n0, acc.x); acc.y = fmaf(v0.y, n0, acc.y);
        acc.z = fmaf(v0.z, n0, acc.z); acc.w = fmaf(v0.w, n0, acc.w);
        acc.x = fmaf(v1.x, n1, acc.x); acc.y = fmaf(v1.y, n1, acc.y);
        acc.z = fmaf(v1.z, n1, acc.z); acc.w = fmaf(v1.w, n1, acc.w);
    }
    if (i < deg) {
        int r0 = g_src[base + i];
        float n0 = g_dis[r0] * dc;
        float4 v0 = load_row4(r0, lane);
        acc.x = fmaf(v0.x, n0, acc.x); acc.y = fmaf(v0.y, n0, acc.y);
        acc.z = fmaf(v0.z, n0, acc.z); acc.w = fmaf(v0.w, n0, acc.w);
    }

    float4 bb = ((const float4*)b)[lane];
    acc.x += bb.x; acc.y += bb.y; acc.z += bb.z; acc.w += bb.w;
    ((float4*)(out + (size_t)node * FEAT))[lane] = acc;
}

// ---------------------------------------------------------------------------
extern "C" void kernel_launch(void* const* d_in, const int* in_sizes, int n_in,
                              void* d_out, int out_size)
{
    const float* x  = (const float*)d_in[0];
    const float* W  = (const float*)d_in[1];
    const float* b  = (const float*)d_in[2];
    const void*  ei = d_in[3];
    float* out = (float*)d_out;

    cudaFuncSetAttribute(gemm_fill_kernel,
                         cudaFuncAttributeMaxDynamicSharedMemorySize, GEMM_SMEM);

    init_wprep_kernel<<<391 + 32, 256>>>((const unsigned int*)ei, W);
    hist_kernel<<<(N_EDGES + 255) / 256, 256>>>(ei);
    scan_kernel<<<N_SBLK, SCAN_BLK>>>();
    gemm_fill_kernel<<<G_GEMM + G_FILL, 256, GEMM_SMEM>>>(x, ei);
    gather_kernel<<<(N_NODES + 7) / 8, 256>>>(b, out);
}

// round 12
// speedup vs baseline: 1.2335x; 1.0002x over previous
#include <cuda_runtime.h>
#include <cuda_bf16.h>
#include <cuda_fp16.h>
#include <cstdint>

#define N_NODES 100000
#define N_EDGES 1600000
#define FEAT 128
#define SCAN_BLK 1024
#define N_SBLK ((N_NODES + SCAN_BLK - 1) / SCAN_BLK)   // 98

#define G_GEMM ((N_NODES + 127) / 128)                 // 782 gemm tile blocks
#define G_FILL 1266                                    // fill blocks in fused grid

// Scratch (static device globals — no allocation).
__device__ __half g_xw[(size_t)N_NODES * FEAT];  // 25.6 MB (fp16 xw)
__device__ float g_dis[N_NODES];
__device__ int   g_degi[N_NODES];
__device__ int   g_base[N_NODES];
__device__ int   g_cur[N_NODES];
__device__ unsigned long long g_sstat[N_SBLK];   // decoupled-lookback status
__device__ int   g_src[N_EDGES];
__device__ int   g_is64;
// W transposed to [n][k] fp16, k-pairs packed in uint32.
__device__ uint32_t g_Wimg[128 * 64];

// ---------------------------------------------------------------------------
__device__ __forceinline__ long long edge_at(const void* p, long long i) {
    if (g_is64) return ((const long long*)p)[i];
    return (long long)((const int*)p)[i];
}

// Fused: blocks [0,391) zero degi + scan status (+detect int64 in block 0);
//        blocks [391,423) transpose W to [n][k] fp16 packed image.
__global__ void init_wprep_kernel(const unsigned int* __restrict__ w,
                                  const float* __restrict__ W) {
    if (blockIdx.x < 391) {
        int i = blockIdx.x * blockDim.x + threadIdx.x;
        if (i < N_NODES) g_degi[i] = 0;
        if (i < N_SBLK) g_sstat[i] = 0ULL;
        if (blockIdx.x == 0 && threadIdx.x == 0) {
            int is64 = 1;
            for (int k = 0; k < 64; k++)
                if (w[2 * k + 1] != 0u) { is64 = 0; break; }
            g_is64 = is64;
        }
    } else {
        int idx = (blockIdx.x - 391) * blockDim.x + threadIdx.x;  // 0..8191
        if (idx >= 8192) return;
        int n  = idx >> 6;
        int kp = idx & 63;
        float v0 = W[(size_t)(2 * kp) * FEAT + n];
        float v1 = W[(size_t)(2 * kp + 1) * FEAT + n];
        __half h0 = __float2half_rn(v0);
        __half h1 = __float2half_rn(v1);
        g_Wimg[n * 64 + kp] = (uint32_t)__half_as_ushort(h0) |
                              ((uint32_t)__half_as_ushort(h1) << 16);
    }
}

__global__ void hist_kernel(const void* __restrict__ ei) {
    int e = blockIdx.x * blockDim.x + threadIdx.x;
    if (e >= N_EDGES) return;
    int c = (int)edge_at(ei, (long long)N_EDGES + e);
    atomicAdd(&g_degi[c], 1);
}

// ---------------------------------------------------------------------------
// Single-pass exclusive scan (decoupled lookback); also dis = rsqrt(deg+1).
// ---------------------------------------------------------------------------
__global__ __launch_bounds__(SCAN_BLK) void scan_kernel() {
    __shared__ int sh[SCAN_BLK];
    __shared__ int s_pref;
    const int bid = blockIdx.x;
    const int tid = threadIdx.x;
    int i = bid * SCAN_BLK + tid;
    int v = (i < N_NODES) ? g_degi[i] : 0;
    if (i < N_NODES) g_dis[i] = rsqrtf((float)v + 1.0f);
    sh[tid] = v;
    __syncthreads();
    #pragma unroll
    for (int off = 1; off < SCAN_BLK; off <<= 1) {
        int t = (tid >= off) ? sh[tid - off] : 0;
        __syncthreads();
        sh[tid] += t;
        __syncthreads();
    }
    int incl = sh[tid];
    if (tid == 0) {
        int total = sh[SCAN_BLK - 1];
        if (bid == 0) {
            atomicExch(&g_sstat[0], (2ULL << 32) | (unsigned)total);
            s_pref = 0;
        } else {
            atomicExch(&g_sstat[bid], (1ULL << 32) | (unsigned)total);
            int pref = 0;
            int j = bid - 1;
            while (true) {
                unsigned long long s;
                do { s = atomicAdd(&g_sstat[j], 0ULL); } while ((s >> 32) == 0ULL);
                pref += (int)(unsigned)s;
                if ((s >> 32) == 2ULL) break;
                j--;
            }
            atomicExch(&g_sstat[bid], (2ULL << 32) | (unsigned)(pref + total));
            s_pref = pref;
        }
    }
    __syncthreads();
    if (i >= N_NODES) return;
    int base = s_pref + incl - v;
    g_base[i] = base;
    g_cur[i]  = base;
}

// ---------------------------------------------------------------------------
// Fused GEMM + fill. GEMM: pure fp16 single term, software-pipelined x loads,
// ldmatrix fragment loads, warp tile 64x32 (2M x 4N warps).
// ---------------------------------------------------------------------------
#define XSP 20   // x tile row stride in uint32 (16 pairs + 4 pad); 80B row
#define WSP 68   // W row stride in uint32 (64 pairs + 4 pad); 272B row
#define GEMM_SMEM ((128 * XSP + 128 * WSP) * 4)   // 45056 bytes

__device__ __forceinline__ void mma_f16(float c[4], const uint32_t a[4],
                                        const uint32_t b[2]) {
    asm volatile(
        "mma.sync.aligned.m16n8k16.row.col.f32.f16.f16.f32 "
        "{%0,%1,%2,%3}, {%4,%5,%6,%7}, {%8,%9}, {%0,%1,%2,%3};"
        : "+f"(c[0]), "+f"(c[1]), "+f"(c[2]), "+f"(c[3])
        : "r"(a[0]), "r"(a[1]), "r"(a[2]), "r"(a[3]), "r"(b[0]), "r"(b[1]));
}

__device__ __forceinline__ void ldsm_x4(uint32_t& r0, uint32_t& r1,
                                        uint32_t& r2, uint32_t& r3,
                                        uint32_t addr) {
    asm volatile(
        "ldmatrix.sync.aligned.m8n8.x4.shared.b16 {%0,%1,%2,%3}, [%4];"
        : "=r"(r0), "=r"(r1), "=r"(r2), "=r"(r3) : "r"(addr));
}

__global__ __launch_bounds__(256) void gemm_fill_kernel(
    const float* __restrict__ x, const void* __restrict__ ei)
{
    if (blockIdx.x >= G_GEMM) {
        long long start = (long long)(blockIdx.x - G_GEMM) * blockDim.x + threadIdx.x;
        for (long long e = start; e < N_EDGES; e += (long long)G_FILL * 256) {
            int r = (int)edge_at(ei, e);
            int c = (int)edge_at(ei, (long long)N_EDGES + e);
            int pos = atomicAdd(&g_cur[c], 1);
            g_src[pos] = r;
        }
        return;
    }

    extern __shared__ uint32_t smem[];
    uint32_t* xs = smem;                       // [128][XSP] fp16 pairs
    uint32_t* ws = xs + 128 * XSP;             // [128][WSP]

    const int tid  = threadIdx.x;
    const int lane = tid & 31;
    const int w    = tid >> 5;
    const int wm   = w & 1;         // M warp: rows 64*wm
    const int wn   = w >> 1;        // N warp: cols 32*wn
    const int grp  = lane >> 2;
    const int qid  = lane & 3;
    const int row0 = blockIdx.x * 128;

    // Copy precomputed W image (L2-resident) into padded SMEM.
    {
        int r = tid >> 1;
        int h = tid & 1;
        const uint4* s = (const uint4*)&g_Wimg[r * 64 + h * 32];
        uint4* d = (uint4*)&ws[r * WSP + h * 32];
        #pragma unroll
        for (int i = 0; i < 8; i++) d[i] = s[i];
    }

    // Preload chunk 0 into registers.
    float4 pre[4];
    #pragma unroll
    for (int i = 0; i < 4; i++) {
        int idx = tid + i * 256;
        int r   = idx >> 3;
        int c4  = idx & 7;
        int gr  = row0 + r;
        pre[i] = make_float4(0.f, 0.f, 0.f, 0.f);
        if (gr < N_NODES)
            pre[i] = *(const float4*)(x + (size_t)gr * FEAT + c4 * 4);
    }

    // ldmatrix base addresses (word offsets added per step).
    // A (per mt): row = 64*wm + 16*mt + (lane&15), kword = xp + (lane>>4)*4
    // B (per nt2): n = 32*wn + 16*nt2 + (lane&7) + ((lane>>4)<<3),
    //              kword = wp + ((lane>>3)&1)*4
    uint32_t xs_base = (uint32_t)__cvta_generic_to_shared(xs);
    uint32_t ws_base = (uint32_t)__cvta_generic_to_shared(ws);
    uint32_t xa[4], wb[2];
    #pragma unroll
    for (int mt = 0; mt < 4; mt++) {
        int row = 64 * wm + 16 * mt + (lane & 15);
        xa[mt] = xs_base + (uint32_t)(row * XSP + (lane >> 4) * 4) * 4u;
    }
    #pragma unroll
    for (int nt2 = 0; nt2 < 2; nt2++) {
        int n = 32 * wn + 16 * nt2 + (lane & 7) + ((lane >> 4) << 3);
        wb[nt2] = ws_base + (uint32_t)(n * WSP + ((lane >> 3) & 1) * 4) * 4u;
    }

    float acc[4][4][4];
    #pragma unroll
    for (int mt = 0; mt < 4; mt++)
        #pragma unroll
        for (int nt = 0; nt < 4; nt++)
            #pragma unroll
            for (int q = 0; q < 4; q++) acc[mt][nt][q] = 0.0f;

    for (int kc = 0; kc < 4; kc++) {            // K chunk = 32
        // Convert + store the prefetched chunk.
        #pragma unroll
        for (int i = 0; i < 4; i++) {
            int idx = tid + i * 256;
            int r   = idx >> 3;
            int c4  = idx & 7;
            __half2 p0 = __float22half2_rn(make_float2(pre[i].x, pre[i].y));
            __half2 p1 = __float22half2_rn(make_float2(pre[i].z, pre[i].w));
            xs[r * XSP + c4 * 2 + 0] = *reinterpret_cast<uint32_t*>(&p0);
            xs[r * XSP + c4 * 2 + 1] = *reinterpret_cast<uint32_t*>(&p1);
        }
        __syncthreads();

        // Issue next chunk's global loads BEFORE the mma phase.
        if (kc < 3) {
            #pragma unroll
            for (int i = 0; i < 4; i++) {
                int idx = tid + i * 256;
                int r   = idx >> 3;
                int c4  = idx & 7;
                int gr  = row0 + r;
                pre[i] = make_float4(0.f, 0.f, 0.f, 0.f);
                if (gr < N_NODES)
                    pre[i] = *(const float4*)(x + (size_t)gr * FEAT +
                                              (kc + 1) * 32 + c4 * 4);
            }
        }

        #pragma unroll
        for (int ks = 0; ks < 2; ks++) {        // two K=16 steps per chunk
            uint32_t xoff = (uint32_t)(ks * 8) * 4u;          // xp words -> bytes
            uint32_t woff = (uint32_t)(kc * 16 + ks * 8) * 4u;

            uint32_t a[4][4];
            #pragma unroll
            for (int mt = 0; mt < 4; mt++)
                ldsm_x4(a[mt][0], a[mt][1], a[mt][2], a[mt][3], xa[mt] + xoff);

            uint32_t b[4][2];
            #pragma unroll
            for (int nt2 = 0; nt2 < 2; nt2++)
                ldsm_x4(b[2*nt2][0], b[2*nt2][1], b[2*nt2+1][0], b[2*nt2+1][1],
                        wb[nt2] + woff);

            #pragma unroll
            for (int nt = 0; nt < 4; nt++)
                #pragma unroll
                for (int mt = 0; mt < 4; mt++)
                    mma_f16(acc[mt][nt], a[mt], b[nt]);
        }
        __syncthreads();
    }

    // Epilogue: write fp16 xw.
    #pragma unroll
    for (int mt = 0; mt < 4; mt++) {
        int r0 = row0 + 64 * wm + 16 * mt + grp;
        #pragma unroll
        for (int nt = 0; nt < 4; nt++) {
            int cb = 32 * wn + 8 * nt + 2 * qid;
            if (r0 < N_NODES)
                *(__half2*)(g_xw + (size_t)r0 * FEAT + cb) =
                    __floats2half2_rn(acc[mt][nt][0], acc[mt][nt][1]);
            if (r0 + 8 < N_NODES)
                *(__half2*)(g_xw + (size_t)(r0 + 8) * FEAT + cb) =
                    __floats2half2_rn(acc[mt][nt][2], acc[mt][nt][3]);
        }
    }
}

// ---------------------------------------------------------------------------
// Gather: one warp per target node; fp16 row reads (8B/lane), fp32 accum.
// ---------------------------------------------------------------------------
__device__ __forceinline__ float4 load_row4(long long node, int lane) {
    uint2 u = *((const uint2*)(g_xw + (size_t)node * FEAT) + lane);
    __half2 p0 = *reinterpret_cast<__half2*>(&u.x);
    __half2 p1 = *reinterpret_cast<__half2*>(&u.y);
    float2 f0 = __half22float2(p0);
    float2 f1 = __half22float2(p1);
    return make_float4(f0.x, f0.y, f1.x, f1.y);
}

__global__ __launch_bounds__(256) void gather_kernel(
    const float* __restrict__ b, float* __restrict__ out)
{
    int node = blockIdx.x * 8 + (threadIdx.x >> 5);
    if (node >= N_NODES) return;
    int lane = threadIdx.x & 31;

    float dc = g_dis[node];
    float d2 = dc * dc;

    float4 acc = load_row4(node, lane);
    acc.x *= d2; acc.y *= d2; acc.z *= d2; acc.w *= d2;   // self-loop

    int base = g_base[node];
    int deg  = g_degi[node];

    int i = 0;
    for (; i + 1 < deg; i += 2) {
        int r0 = g_src[base + i];
        int r1 = g_src[base + i + 1];
        float n0 = g_dis[r0] * dc;
        float n1 = g_dis[r1] * dc;
        float4 v0 = load_row4(r0, lane);
        float4 v1 = load_row4(r1, lane);
        acc.x = fmaf(v0.x, n0, acc.x); acc.y = fmaf(v0.y, n0, acc.y);
        acc.z = fmaf(v0.z, n0, acc.z); acc.w = fmaf(v0.w, n0, acc.w);
        acc.x = fmaf(v1.x, n1, acc.x); acc.y = fmaf(v1.y, n1, acc.y);
        acc.z = fmaf(v1.z, n1, acc.z); acc.w = fmaf(v1.w, n1, acc.w);
    }
    if (i < deg) {
        int r0 = g_src[base + i];
        float n0 = g_dis[r0] * dc;
        float4 v0 = load_row4(r0, lane);
        acc.x = fmaf(v0.x, n0, acc.x); acc.y = fmaf(v0.y, n0, acc.y);
        acc.z = fmaf(v0.z, n0, acc.z); acc.w = fmaf(v0.w, n0, acc.w);
    }

    float4 bb = ((const float4*)b)[lane];
    acc.x += bb.x; acc.y += bb.y; acc.z += bb.z; acc.w += bb.w;
    ((float4*)(out + (size_t)node * FEAT))[lane] = acc;
}

// ---------------------------------------------------------------------------
extern "C" void kernel_launch(void* const* d_in, const int* in_sizes, int n_in,
                              void* d_out, int out_size)
{
    const float* x  = (const float*)d_in[0];
    const float* W  = (const float*)d_in[1];
    const float* b  = (const float*)d_in[2];
    const void*  ei = d_in[3];
    float* out = (float*)d_out;

    cudaFuncSetAttribute(gemm_fill_kernel,
                         cudaFuncAttributeMaxDynamicSharedMemorySize, GEMM_SMEM);

    init_wprep_kernel<<<391 + 32, 256>>>((const unsigned int*)ei, W);
    hist_kernel<<<(N_EDGES + 255) / 256, 256>>>(ei);
    scan_kernel<<<N_SBLK, SCAN_BLK>>>();
    gemm_fill_kernel<<<G_GEMM + G_FILL, 256, GEMM_SMEM>>>(x, ei);
    gather_kernel<<<(N_NODES + 7) / 8, 256>>>(b, out);
}